// round 10
// baseline (speedup 1.0000x reference)
#include <cuda_runtime.h>
#include <cstdint>

// y = x @ (scale*(Wq - zp))^T + bias
// x [8192,4096] fp32, Wq [4096,4096] i32, out [8192,4096] fp32.
#define M_TOTAL 8192
#define K_TOTAL 4096
#define N_TOTAL 4096

static constexpr int TM = 128;
static constexpr int TN = 128;
static constexpr int KC = 128;           // 128 int8 = 128B rows (one SW128 block)
static constexpr int NK = K_TOTAL / KC;  // 32
static constexpr int NT = (M_TOTAL / TM) * (N_TOTAL / TN);  // 2048 tiles
static constexpr int GRID = 148;         // persistent: one CTA per SM
static constexpr int AH_OFF = 0;
static constexpr int AL_OFF = 16384;
static constexpr int B_OFF  = 32768;
static constexpr int STAGE_BYTES = 49152;               // Ah 16K + Al 16K + B 16K
static constexpr int SMEM_BYTES = 4 * STAGE_BYTES;      // 196608

// x quantization: q = round(x*2048), q = 256*h + l (h,l int8)
static constexpr float QSCALE = 2048.0f;

// prep grid split: W blocks then X blocks (1024 elems per block each)
static constexpr int WBLOCKS = (N_TOTAL * K_TOTAL) / 1024;          // 16384
static constexpr int XBLOCKS = (M_TOTAL * K_TOTAL) / 1024;          // 32768
static constexpr int QROWS   = M_TOTAL * 4;                         // quarter-rows

// ---------------- scratch (device globals: allocation-free) ----------------
__device__ __align__(1024) char g_Ah[(size_t)M_TOTAL * K_TOTAL];  // 32 MB
__device__ __align__(1024) char g_Al[(size_t)M_TOTAL * K_TOTAL];  // 32 MB
__device__ __align__(1024) char g_Bw[(size_t)N_TOTAL * K_TOTAL];  // 16 MB
__device__ int g_part[QROWS];   // per-quarter-row q sums (plain stores, no init needed)

// ---------------- helpers ----------------
__device__ __forceinline__ uint32_t smem_u32(const void* p) {
    uint32_t a;
    asm("{ .reg .u64 t; cvta.to.shared.u64 t, %1; cvt.u32.u64 %0, t; }" : "=r"(a) : "l"(p));
    return a;
}
__device__ __forceinline__ uint32_t sw128(uint32_t off) {
    return off ^ ((off >> 3) & 0x70);
}
#define CP_ASYNC16(dst, src) \
    asm volatile("cp.async.cg.shared.global [%0], [%1], 16;" :: "r"(dst), "l"(src) : "memory")
#define CP_COMMIT() asm volatile("cp.async.commit_group;" ::: "memory")
#define CP_WAIT2()  asm volatile("cp.async.wait_group 2;" ::: "memory")

__device__ __forceinline__ void ldsm_x4(uint32_t& r0, uint32_t& r1, uint32_t& r2, uint32_t& r3,
                                        uint32_t addr) {
    asm volatile("ldmatrix.sync.aligned.m8n8.x4.shared.b16 {%0,%1,%2,%3}, [%4];"
                 : "=r"(r0), "=r"(r1), "=r"(r2), "=r"(r3) : "r"(addr));
}
__device__ __forceinline__ void imma16832(int32_t* c, const uint32_t* a, uint32_t b0, uint32_t b1) {
    asm volatile(
        "mma.sync.aligned.m16n8k32.row.col.s32.s8.s8.s32 "
        "{%0,%1,%2,%3}, {%4,%5,%6,%7}, {%8,%9}, {%0,%1,%2,%3};"
        : "+r"(c[0]), "+r"(c[1]), "+r"(c[2]), "+r"(c[3])
        : "r"(a[0]), "r"(a[1]), "r"(a[2]), "r"(a[3]), "r"(b0), "r"(b1));
}

// Supertiled mapping: groups of 8 N-tiles across all M-tiles (L2 reuse)
__device__ __forceinline__ void tile_mn(int t, int& m0, int& n0) {
    const int grp = t >> 9;        // / 512
    const int rem = t & 511;
    m0 = (rem >> 3) * TM;
    n0 = ((grp << 3) + (rem & 7)) * TN;
}

// ---------------- merged prep kernel ----------------
// Blocks [0, WBLOCKS): W int32 -> int8 (v - round(zp)).
// Blocks [WBLOCKS, WBLOCKS+XBLOCKS): x fp32 -> (h,l) int8 split + quarter-row q-sums.
__global__ void __launch_bounds__(256)
prep_kernel(const float* __restrict__ x, const int* __restrict__ wq,
            const float* __restrict__ zp_p) {
    const int b = blockIdx.x;
    const int tid = threadIdx.x;
    if (b < WBLOCKS) {
        const int zpr = lrintf(*zp_p);
        const size_t i = ((size_t)b * 256 + tid) * 4;
        int4 v = *reinterpret_cast<const int4*>(wq + i);
        char4 w;
        w.x = (char)(v.x - zpr);
        w.y = (char)(v.y - zpr);
        w.z = (char)(v.z - zpr);
        w.w = (char)(v.w - zpr);
        *reinterpret_cast<char4*>(&g_Bw[i]) = w;
    } else {
        __shared__ int red[8];
        const int xb = b - WBLOCKS;                    // quarter-row index
        const size_t i = ((size_t)xb * 256 + tid) * 4; // elem index into x
        float4 v = *reinterpret_cast<const float4*>(x + i);
        int q0 = min(max(__float2int_rn(v.x * QSCALE), -32640), 32639);
        int q1 = min(max(__float2int_rn(v.y * QSCALE), -32640), 32639);
        int q2 = min(max(__float2int_rn(v.z * QSCALE), -32640), 32639);
        int q3 = min(max(__float2int_rn(v.w * QSCALE), -32640), 32639);
        int h0 = (q0 + 128) >> 8, h1 = (q1 + 128) >> 8;
        int h2 = (q2 + 128) >> 8, h3 = (q3 + 128) >> 8;
        char4 hc, lc;
        hc.x = (char)h0; hc.y = (char)h1; hc.z = (char)h2; hc.w = (char)h3;
        lc.x = (char)(q0 - (h0 << 8)); lc.y = (char)(q1 - (h1 << 8));
        lc.z = (char)(q2 - (h2 << 8)); lc.w = (char)(q3 - (h3 << 8));
        *reinterpret_cast<char4*>(&g_Ah[i]) = hc;
        *reinterpret_cast<char4*>(&g_Al[i]) = lc;
        // block-level partial sum for this quarter-row (plain store, no init needed)
        int s = q0 + q1 + q2 + q3;
#pragma unroll
        for (int o = 16; o; o >>= 1) s += __shfl_down_sync(0xFFFFFFFFu, s, o);
        if ((tid & 31) == 0) red[tid >> 5] = s;
        __syncthreads();
        if (tid == 0) {
            int t = red[0] + red[1] + red[2] + red[3] + red[4] + red[5] + red[6] + red[7];
            g_part[xb] = t;
        }
    }
}

// ---------------- persistent GEMM: 128x128 tiles, 8 warps (2m x 4n), s8 IMMA ----------------
__global__ void __launch_bounds__(256, 1)
gemm_kernel(const float* __restrict__ bias, const float* __restrict__ scale_p,
            const float* __restrict__ zp_p, float* __restrict__ out) {
    extern __shared__ char smem[];
    const uint32_t sb = smem_u32(smem);
    const int tid = threadIdx.x;
    const int wid = tid >> 5;
    const int lane = tid & 31;
    const int bid = blockIdx.x;

    const int wm = wid >> 2;   // 0..1 -> 64 rows
    const int wn = wid & 3;    // 0..3 -> 32 cols

    // ---- cp.async mapping: 8x16B chunks per 128B row, 32 rows/pass, 4 passes/tile ----
    const int chunk = tid & 7;
    const int row0 = tid >> 3;  // 0..31
    uint32_t dst_off[4];
#pragma unroll
    for (int j = 0; j < 4; j++)
        dst_off[j] = sw128((uint32_t)(row0 + 32 * j) * 128u + (uint32_t)chunk * 16u);

    // ---- load-side state (uniform across CTA) ----
    int lt = bid;   // tile being loaded
    int lkc = 0;    // next k-chunk to load within lt
    const char *pAh, *pAl, *pB;
    auto set_load_tile = [&](int t) {
        int m0_, n0_;
        tile_mn(t, m0_, n0_);
        pAh = g_Ah + (size_t)m0_ * K_TOTAL + chunk * 16;
        pAl = g_Al + (size_t)m0_ * K_TOTAL + chunk * 16;
        pB  = g_Bw + (size_t)n0_ * K_TOTAL + chunk * 16;
    };
    set_load_tile(lt);

    auto load_chunk = [&](int buf) {
        const uint32_t tb = sb + (uint32_t)buf * STAGE_BYTES;
        const size_t koff = (size_t)lkc * KC;
#pragma unroll
        for (int j = 0; j < 4; j++) {
            const size_t roff = (size_t)(row0 + 32 * j) * K_TOTAL + koff;
            CP_ASYNC16(tb + AH_OFF + dst_off[j], pAh + roff);
            CP_ASYNC16(tb + AL_OFF + dst_off[j], pAl + roff);
            CP_ASYNC16(tb + B_OFF  + dst_off[j], pB  + roff);
        }
        CP_COMMIT();
        if (++lkc == NK) {
            lkc = 0;
            lt += GRID;
            if (lt < NT) set_load_tile(lt);
        }
    };

    // ---- ldmatrix lane addressing (int8: 16B column units) ----
    const int lmat = lane >> 3;
    const int lrow = lane & 7;
    uint32_t a_off[4];
#pragma unroll
    for (int tm = 0; tm < 4; tm++) {
        uint32_t r = (uint32_t)(wm * 64 + tm * 16 + lrow + ((lmat & 1) << 3));
        uint32_t c = (uint32_t)((lmat >> 1) << 4);
        a_off[tm] = sw128(r * 128u + c);
    }
    uint32_t b_off[2];
#pragma unroll
    for (int p = 0; p < 2; p++) {
        uint32_t r = (uint32_t)(wn * 32 + p * 16 + lrow + ((lmat >> 1) << 3));
        uint32_t c = (uint32_t)((lmat & 1) << 4);
        b_off[p] = sw128(r * 128u + c) + B_OFF;
    }

    int32_t acch[4][4][4], accl[4][4][4];
#pragma unroll
    for (int i = 0; i < 4; i++)
#pragma unroll
        for (int j = 0; j < 4; j++)
#pragma unroll
            for (int k = 0; k < 4; k++) { acch[i][j][k] = 0; accl[i][j][k] = 0; }

    uint32_t ah[4][4], al[4][4], rb0[2][4], rb1[2][4];

    auto ld_A = [&](uint32_t base, int ks, uint32_t (&dst)[4][4]) {
        const uint32_t kbyte = (uint32_t)ks * 32u;  // bits 5..6 only; XOR == add under sw128
#pragma unroll
        for (int tm = 0; tm < 4; tm++)
            ldsm_x4(dst[tm][0], dst[tm][1], dst[tm][2], dst[tm][3],
                    base + (a_off[tm] ^ kbyte));
    };
    auto ld_B = [&](int db, uint32_t tb, int ks) {
        const uint32_t kbyte = (uint32_t)ks * 32u;
#pragma unroll
        for (int p = 0; p < 2; p++) {
            uint32_t r0, r1, r2, r3;
            ldsm_x4(r0, r1, r2, r3, tb + (b_off[p] ^ kbyte));
            rb0[db][2 * p] = r0;     rb1[db][2 * p] = r1;
            rb0[db][2 * p + 1] = r2; rb1[db][2 * p + 1] = r3;
        }
    };

    // ---- prologue: 3 chunks in flight ----
    load_chunk(0);
    load_chunk(1);
    load_chunk(2);

    const float sd = (*scale_p) * (1.0f / QSCALE);
    const float czp = (float)lrintf(*zp_p) - (*zp_p);

    int buf = 0;
    for (int ct = bid; ct < NT; ct += GRID) {
        int m0, n0;
        tile_mn(ct, m0, n0);

        for (int kc = 0; kc < NK; ++kc) {
            CP_WAIT2();            // chunk in `buf` resident
            __syncthreads();       // all warps done reading buffer (buf+3)&3
            if (lt < NT) load_chunk((buf + 3) & 3);
            else CP_COMMIT();      // keep wait_group accounting

            const uint32_t tb = sb + (uint32_t)buf * STAGE_BYTES;
            ld_B(0, tb, 0);
#pragma unroll
            for (int ks = 0; ks < 4; ++ks) {
                const int cur = ks & 1;
                ld_A(tb + AH_OFF, ks, ah);
                ld_A(tb + AL_OFF, ks, al);
                if (ks < 3) ld_B(cur ^ 1, tb, ks + 1);
                // interleave h/l MMAs per (tm,tn): adjacent instrs hit independent accs
#pragma unroll
                for (int tm = 0; tm < 4; tm++)
#pragma unroll
                    for (int tn = 0; tn < 4; tn++) {
                        imma16832(acch[tm][tn], ah[tm], rb0[cur][tn], rb1[cur][tn]);
                        imma16832(accl[tm][tn], al[tm], rb0[cur][tn], rb1[cur][tn]);
                    }
            }
            buf = (buf + 1) & 3;
        }

        // ---- epilogue: y = (256*Sh + Sl + c*rowsum_q)*(scale/2048) + bias ----
        const int r_base = m0 + wm * 64 + (lane >> 2);
        const int c_base = n0 + wn * 32 + (lane & 3) * 2;
#pragma unroll
        for (int tm = 0; tm < 4; tm++) {
            const int row = r_base + tm * 16;
            const int rs0 = g_part[row * 4] + g_part[row * 4 + 1]
                          + g_part[row * 4 + 2] + g_part[row * 4 + 3];
            const int rs1 = g_part[(row + 8) * 4] + g_part[(row + 8) * 4 + 1]
                          + g_part[(row + 8) * 4 + 2] + g_part[(row + 8) * 4 + 3];
            const float radd0 = czp * (float)rs0 * sd;
            const float radd1 = czp * (float)rs1 * sd;
#pragma unroll
            for (int tn = 0; tn < 4; tn++) {
                const int col = c_base + tn * 8;
                const float2 bv = *reinterpret_cast<const float2*>(bias + col);
                float t0 = fmaf(256.0f, (float)acch[tm][tn][0], (float)accl[tm][tn][0]);
                float t1 = fmaf(256.0f, (float)acch[tm][tn][1], (float)accl[tm][tn][1]);
                float t2 = fmaf(256.0f, (float)acch[tm][tn][2], (float)accl[tm][tn][2]);
                float t3 = fmaf(256.0f, (float)acch[tm][tn][3], (float)accl[tm][tn][3]);
                float2 o0, o1;
                o0.x = fmaf(t0, sd, bv.x + radd0);
                o0.y = fmaf(t1, sd, bv.y + radd0);
                o1.x = fmaf(t2, sd, bv.x + radd1);
                o1.y = fmaf(t3, sd, bv.y + radd1);
                *reinterpret_cast<float2*>(out + (size_t)row * N_TOTAL + col) = o0;
                *reinterpret_cast<float2*>(out + (size_t)(row + 8) * N_TOTAL + col) = o1;
                acch[tm][tn][0] = 0; acch[tm][tn][1] = 0; acch[tm][tn][2] = 0; acch[tm][tn][3] = 0;
                accl[tm][tn][0] = 0; accl[tm][tn][1] = 0; accl[tm][tn][2] = 0; accl[tm][tn][3] = 0;
            }
        }
    }
}

// ---------------- launch ----------------
extern "C" void kernel_launch(void* const* d_in, const int* in_sizes, int n_in,
                              void* d_out, int out_size) {
    const float* x     = (const float*)d_in[0];
    const int*   wq    = (const int*)  d_in[1];
    const float* bias  = (const float*)d_in[2];
    const float* scale = (const float*)d_in[3];
    const float* zp    = (const float*)d_in[4];
    float* out = (float*)d_out;

    cudaFuncSetAttribute(gemm_kernel, cudaFuncAttributeMaxDynamicSharedMemorySize, SMEM_BYTES);

    prep_kernel<<<WBLOCKS + XBLOCKS, 256>>>(x, wq, zp);
    gemm_kernel<<<GRID, 256, SMEM_BYTES>>>(bias, scale, zp, out);
}

// round 11
// speedup vs baseline: 1.0498x; 1.0498x over previous
#include <cuda_runtime.h>
#include <cstdint>

// y = x @ (scale*(Wq - zp))^T + bias
// x [8192,4096] fp32, Wq [4096,4096] i32, out [8192,4096] fp32.
#define M_TOTAL 8192
#define K_TOTAL 4096
#define N_TOTAL 4096

static constexpr int TM = 128;
static constexpr int TN = 128;
static constexpr int KC = 128;           // 128 int8 = 128B rows (one SW128 block)
static constexpr int NK = K_TOTAL / KC;  // 32
static constexpr int NT = (M_TOTAL / TM) * (N_TOTAL / TN);  // 2048 tiles
static constexpr int GRID = 148;         // persistent: one CTA per SM
static constexpr int THREADS = 512;      // 16 warps: 4m x 4n, 32x32 warp tiles
static constexpr int AH_OFF = 0;
static constexpr int AL_OFF = 16384;
static constexpr int B_OFF  = 32768;
static constexpr int STAGE_BYTES = 49152;               // Ah 16K + Al 16K + B 16K
static constexpr int SMEM_BYTES = 4 * STAGE_BYTES;      // 196608

// x quantization: q = round(x*2048), q = 256*h + l (h,l int8)
static constexpr float QSCALE = 2048.0f;

// prep grid split: W blocks then X blocks (1024 elems per block each)
static constexpr int WBLOCKS = (N_TOTAL * K_TOTAL) / 1024;          // 16384
static constexpr int XBLOCKS = (M_TOTAL * K_TOTAL) / 1024;          // 32768
static constexpr int QROWS   = M_TOTAL * 4;                         // quarter-rows

// ---------------- scratch (device globals: allocation-free) ----------------
__device__ __align__(1024) char g_Ah[(size_t)M_TOTAL * K_TOTAL];  // 32 MB
__device__ __align__(1024) char g_Al[(size_t)M_TOTAL * K_TOTAL];  // 32 MB
__device__ __align__(1024) char g_Bw[(size_t)N_TOTAL * K_TOTAL];  // 16 MB
__device__ int g_part[QROWS];   // per-quarter-row q sums (plain stores, no init needed)

// ---------------- helpers ----------------
__device__ __forceinline__ uint32_t smem_u32(const void* p) {
    uint32_t a;
    asm("{ .reg .u64 t; cvta.to.shared.u64 t, %1; cvt.u32.u64 %0, t; }" : "=r"(a) : "l"(p));
    return a;
}
__device__ __forceinline__ uint32_t sw128(uint32_t off) {
    return off ^ ((off >> 3) & 0x70);
}
#define CP_ASYNC16(dst, src) \
    asm volatile("cp.async.cg.shared.global [%0], [%1], 16;" :: "r"(dst), "l"(src) : "memory")
#define CP_COMMIT() asm volatile("cp.async.commit_group;" ::: "memory")
#define CP_WAIT2()  asm volatile("cp.async.wait_group 2;" ::: "memory")

__device__ __forceinline__ void ldsm_x4(uint32_t& r0, uint32_t& r1, uint32_t& r2, uint32_t& r3,
                                        uint32_t addr) {
    asm volatile("ldmatrix.sync.aligned.m8n8.x4.shared.b16 {%0,%1,%2,%3}, [%4];"
                 : "=r"(r0), "=r"(r1), "=r"(r2), "=r"(r3) : "r"(addr));
}
__device__ __forceinline__ void imma16832(int32_t* c, const uint32_t* a, uint32_t b0, uint32_t b1) {
    asm volatile(
        "mma.sync.aligned.m16n8k32.row.col.s32.s8.s8.s32 "
        "{%0,%1,%2,%3}, {%4,%5,%6,%7}, {%8,%9}, {%0,%1,%2,%3};"
        : "+r"(c[0]), "+r"(c[1]), "+r"(c[2]), "+r"(c[3])
        : "r"(a[0]), "r"(a[1]), "r"(a[2]), "r"(a[3]), "r"(b0), "r"(b1));
}

// Supertiled mapping: groups of 8 N-tiles across all M-tiles (L2 reuse)
__device__ __forceinline__ void tile_mn(int t, int& m0, int& n0) {
    const int grp = t >> 9;        // / 512
    const int rem = t & 511;
    m0 = (rem >> 3) * TM;
    n0 = ((grp << 3) + (rem & 7)) * TN;
}

// ---------------- merged prep kernel ----------------
__global__ void __launch_bounds__(256)
prep_kernel(const float* __restrict__ x, const int* __restrict__ wq,
            const float* __restrict__ zp_p) {
    const int b = blockIdx.x;
    const int tid = threadIdx.x;
    if (b < WBLOCKS) {
        const int zpr = lrintf(*zp_p);
        const size_t i = ((size_t)b * 256 + tid) * 4;
        int4 v = *reinterpret_cast<const int4*>(wq + i);
        char4 w;
        w.x = (char)(v.x - zpr);
        w.y = (char)(v.y - zpr);
        w.z = (char)(v.z - zpr);
        w.w = (char)(v.w - zpr);
        *reinterpret_cast<char4*>(&g_Bw[i]) = w;
    } else {
        __shared__ int red[8];
        const int xb = b - WBLOCKS;                    // quarter-row index
        const size_t i = ((size_t)xb * 256 + tid) * 4;
        float4 v = *reinterpret_cast<const float4*>(x + i);
        int q0 = min(max(__float2int_rn(v.x * QSCALE), -32640), 32639);
        int q1 = min(max(__float2int_rn(v.y * QSCALE), -32640), 32639);
        int q2 = min(max(__float2int_rn(v.z * QSCALE), -32640), 32639);
        int q3 = min(max(__float2int_rn(v.w * QSCALE), -32640), 32639);
        int h0 = (q0 + 128) >> 8, h1 = (q1 + 128) >> 8;
        int h2 = (q2 + 128) >> 8, h3 = (q3 + 128) >> 8;
        char4 hc, lc;
        hc.x = (char)h0; hc.y = (char)h1; hc.z = (char)h2; hc.w = (char)h3;
        lc.x = (char)(q0 - (h0 << 8)); lc.y = (char)(q1 - (h1 << 8));
        lc.z = (char)(q2 - (h2 << 8)); lc.w = (char)(q3 - (h3 << 8));
        *reinterpret_cast<char4*>(&g_Ah[i]) = hc;
        *reinterpret_cast<char4*>(&g_Al[i]) = lc;
        int s = q0 + q1 + q2 + q3;
#pragma unroll
        for (int o = 16; o; o >>= 1) s += __shfl_down_sync(0xFFFFFFFFu, s, o);
        if ((tid & 31) == 0) red[tid >> 5] = s;
        __syncthreads();
        if (tid == 0) {
            int t = red[0] + red[1] + red[2] + red[3] + red[4] + red[5] + red[6] + red[7];
            g_part[xb] = t;
        }
    }
}

// ---------------- persistent GEMM: 128x128 tiles, 16 warps (4m x 4n), s8 IMMA ----------------
__global__ void __launch_bounds__(THREADS, 1)
gemm_kernel(const float* __restrict__ bias, const float* __restrict__ scale_p,
            const float* __restrict__ zp_p, float* __restrict__ out) {
    extern __shared__ char smem[];
    const uint32_t sb = smem_u32(smem);
    const int tid = threadIdx.x;
    const int wid = tid >> 5;
    const int lane = tid & 31;
    const int bid = blockIdx.x;

    const int wm = wid >> 2;   // 0..3 -> 32 rows
    const int wn = wid & 3;    // 0..3 -> 32 cols

    // ---- cp.async mapping: 8x16B chunks per 128B row, 64 rows/pass, 2 passes/tile ----
    const int chunk = tid & 7;
    const int row0 = tid >> 3;  // 0..63
    uint32_t dst_off[2];
#pragma unroll
    for (int j = 0; j < 2; j++)
        dst_off[j] = sw128((uint32_t)(row0 + 64 * j) * 128u + (uint32_t)chunk * 16u);

    // ---- load-side state (uniform across CTA) ----
    int lt = bid;   // tile being loaded
    int lkc = 0;    // next k-chunk to load within lt
    const char *pAh, *pAl, *pB;
    auto set_load_tile = [&](int t) {
        int m0_, n0_;
        tile_mn(t, m0_, n0_);
        pAh = g_Ah + (size_t)m0_ * K_TOTAL + chunk * 16;
        pAl = g_Al + (size_t)m0_ * K_TOTAL + chunk * 16;
        pB  = g_Bw + (size_t)n0_ * K_TOTAL + chunk * 16;
    };
    set_load_tile(lt);

    auto load_chunk = [&](int buf) {
        const uint32_t tb = sb + (uint32_t)buf * STAGE_BYTES;
        const size_t koff = (size_t)lkc * KC;
#pragma unroll
        for (int j = 0; j < 2; j++) {
            const size_t roff = (size_t)(row0 + 64 * j) * K_TOTAL + koff;
            CP_ASYNC16(tb + AH_OFF + dst_off[j], pAh + roff);
            CP_ASYNC16(tb + AL_OFF + dst_off[j], pAl + roff);
            CP_ASYNC16(tb + B_OFF  + dst_off[j], pB  + roff);
        }
        CP_COMMIT();
        if (++lkc == NK) {
            lkc = 0;
            lt += GRID;
            if (lt < NT) set_load_tile(lt);
        }
    };

    // ---- ldmatrix lane addressing (int8: 16B column units) ----
    const int lmat = lane >> 3;
    const int lrow = lane & 7;
    uint32_t a_off[2];
#pragma unroll
    for (int tm = 0; tm < 2; tm++) {
        uint32_t r = (uint32_t)(wm * 32 + tm * 16 + lrow + ((lmat & 1) << 3));
        uint32_t c = (uint32_t)((lmat >> 1) << 4);
        a_off[tm] = sw128(r * 128u + c);
    }
    uint32_t b_off[2];
#pragma unroll
    for (int p = 0; p < 2; p++) {
        uint32_t r = (uint32_t)(wn * 32 + p * 16 + lrow + ((lmat >> 1) << 3));
        uint32_t c = (uint32_t)((lmat & 1) << 4);
        b_off[p] = sw128(r * 128u + c) + B_OFF;
    }

    int32_t acch[2][4][4], accl[2][4][4];
#pragma unroll
    for (int i = 0; i < 2; i++)
#pragma unroll
        for (int j = 0; j < 4; j++)
#pragma unroll
            for (int k = 0; k < 4; k++) { acch[i][j][k] = 0; accl[i][j][k] = 0; }

    uint32_t ah[2][4], al[2][4], rb0[4], rb1[4];

    // ---- prologue: 3 chunks in flight ----
    load_chunk(0);
    load_chunk(1);
    load_chunk(2);

    const float sd = (*scale_p) * (1.0f / QSCALE);
    const float czp = (float)lrintf(*zp_p) - (*zp_p);

    int buf = 0;
    for (int ct = bid; ct < NT; ct += GRID) {
        int m0, n0;
        tile_mn(ct, m0, n0);

        for (int kc = 0; kc < NK; ++kc) {
            CP_WAIT2();            // chunk in `buf` resident
            __syncthreads();       // all warps done reading buffer (buf+3)&3
            if (lt < NT) load_chunk((buf + 3) & 3);
            else CP_COMMIT();      // keep wait_group accounting

            const uint32_t tb = sb + (uint32_t)buf * STAGE_BYTES;
#pragma unroll
            for (int ks = 0; ks < 4; ++ks) {
                const uint32_t kbyte = (uint32_t)ks * 32u;  // bits 5..6; XOR == add under sw128
                // B fragments (shared by h and l passes)
#pragma unroll
                for (int p = 0; p < 2; p++) {
                    uint32_t r0, r1, r2, r3;
                    ldsm_x4(r0, r1, r2, r3, tb + (b_off[p] ^ kbyte));
                    rb0[2 * p] = r0;     rb1[2 * p] = r1;
                    rb0[2 * p + 1] = r2; rb1[2 * p + 1] = r3;
                }
#pragma unroll
                for (int tm = 0; tm < 2; tm++)
                    ldsm_x4(ah[tm][0], ah[tm][1], ah[tm][2], ah[tm][3],
                            tb + AH_OFF + (a_off[tm] ^ kbyte));
#pragma unroll
                for (int tm = 0; tm < 2; tm++)
                    ldsm_x4(al[tm][0], al[tm][1], al[tm][2], al[tm][3],
                            tb + AL_OFF + (a_off[tm] ^ kbyte));
#pragma unroll
                for (int tm = 0; tm < 2; tm++)
#pragma unroll
                    for (int tn = 0; tn < 4; tn++) {
                        imma16832(acch[tm][tn], ah[tm], rb0[tn], rb1[tn]);
                        imma16832(accl[tm][tn], al[tm], rb0[tn], rb1[tn]);
                    }
            }
            buf = (buf + 1) & 3;
        }

        // ---- epilogue: y = (256*Sh + Sl + c*rowsum_q)*(scale/2048) + bias ----
        const int r_base = m0 + wm * 32 + (lane >> 2);
        const int c_base = n0 + wn * 32 + (lane & 3) * 2;
#pragma unroll
        for (int tm = 0; tm < 2; tm++) {
            const int row = r_base + tm * 16;
            const int rs0 = g_part[row * 4] + g_part[row * 4 + 1]
                          + g_part[row * 4 + 2] + g_part[row * 4 + 3];
            const int rs1 = g_part[(row + 8) * 4] + g_part[(row + 8) * 4 + 1]
                          + g_part[(row + 8) * 4 + 2] + g_part[(row + 8) * 4 + 3];
            const float radd0 = czp * (float)rs0 * sd;
            const float radd1 = czp * (float)rs1 * sd;
#pragma unroll
            for (int tn = 0; tn < 4; tn++) {
                const int col = c_base + tn * 8;
                const float2 bv = *reinterpret_cast<const float2*>(bias + col);
                float t0 = fmaf(256.0f, (float)acch[tm][tn][0], (float)accl[tm][tn][0]);
                float t1 = fmaf(256.0f, (float)acch[tm][tn][1], (float)accl[tm][tn][1]);
                float t2 = fmaf(256.0f, (float)acch[tm][tn][2], (float)accl[tm][tn][2]);
                float t3 = fmaf(256.0f, (float)acch[tm][tn][3], (float)accl[tm][tn][3]);
                float2 o0, o1;
                o0.x = fmaf(t0, sd, bv.x + radd0);
                o0.y = fmaf(t1, sd, bv.y + radd0);
                o1.x = fmaf(t2, sd, bv.x + radd1);
                o1.y = fmaf(t3, sd, bv.y + radd1);
                *reinterpret_cast<float2*>(out + (size_t)row * N_TOTAL + col) = o0;
                *reinterpret_cast<float2*>(out + (size_t)(row + 8) * N_TOTAL + col) = o1;
                acch[tm][tn][0] = 0; acch[tm][tn][1] = 0; acch[tm][tn][2] = 0; acch[tm][tn][3] = 0;
                accl[tm][tn][0] = 0; accl[tm][tn][1] = 0; accl[tm][tn][2] = 0; accl[tm][tn][3] = 0;
            }
        }
    }
}

// ---------------- launch ----------------
extern "C" void kernel_launch(void* const* d_in, const int* in_sizes, int n_in,
                              void* d_out, int out_size) {
    const float* x     = (const float*)d_in[0];
    const int*   wq    = (const int*)  d_in[1];
    const float* bias  = (const float*)d_in[2];
    const float* scale = (const float*)d_in[3];
    const float* zp    = (const float*)d_in[4];
    float* out = (float*)d_out;

    cudaFuncSetAttribute(gemm_kernel, cudaFuncAttributeMaxDynamicSharedMemorySize, SMEM_BYTES);

    prep_kernel<<<WBLOCKS + XBLOCKS, 256>>>(x, wq, zp);
    gemm_kernel<<<GRID, THREADS, SMEM_BYTES>>>(bias, scale, zp, out);
}

// round 12
// speedup vs baseline: 1.0642x; 1.0137x over previous
#include <cuda_runtime.h>
#include <cstdint>

// y = x @ (scale*(Wq - zp))^T + bias
// x [8192,4096] fp32, Wq [4096,4096] i32, out [8192,4096] fp32.
#define M_TOTAL 8192
#define K_TOTAL 4096
#define N_TOTAL 4096

static constexpr int TM = 64;
static constexpr int TN = 128;
static constexpr int KC = 128;           // 128 int8 = 128B rows (one SW128 block)
static constexpr int NK = K_TOTAL / KC;  // 32
static constexpr int NT = (M_TOTAL / TM) * (N_TOTAL / TN);  // 4096 tiles
static constexpr int GRID = 296;         // persistent: two CTAs per SM
static constexpr int THREADS = 256;      // 8 warps: 2m x 4n, 32x32 warp tiles
static constexpr int AH_OFF = 0;
static constexpr int AL_OFF = 8192;
static constexpr int B_OFF  = 16384;
static constexpr int STAGE_BYTES = 32768;               // Ah 8K + Al 8K + B 16K
static constexpr int SMEM_BYTES = 3 * STAGE_BYTES;      // 98304 (x2 CTAs = 192KB/SM)

// x quantization: q = round(x*2048), q = 256*h + l (h,l int8)
static constexpr float QSCALE = 2048.0f;

// prep grid split: W blocks then X blocks (1024 elems per block each)
static constexpr int WBLOCKS = (N_TOTAL * K_TOTAL) / 1024;          // 16384
static constexpr int XBLOCKS = (M_TOTAL * K_TOTAL) / 1024;          // 32768
static constexpr int QROWS   = M_TOTAL * 4;                         // quarter-rows

// ---------------- scratch (device globals: allocation-free) ----------------
__device__ __align__(1024) char g_Ah[(size_t)M_TOTAL * K_TOTAL];  // 32 MB
__device__ __align__(1024) char g_Al[(size_t)M_TOTAL * K_TOTAL];  // 32 MB
__device__ __align__(1024) char g_Bw[(size_t)N_TOTAL * K_TOTAL];  // 16 MB
__device__ int g_part[QROWS];   // per-quarter-row q sums (plain stores, no init needed)

// ---------------- helpers ----------------
__device__ __forceinline__ uint32_t smem_u32(const void* p) {
    uint32_t a;
    asm("{ .reg .u64 t; cvta.to.shared.u64 t, %1; cvt.u32.u64 %0, t; }" : "=r"(a) : "l"(p));
    return a;
}
__device__ __forceinline__ uint32_t sw128(uint32_t off) {
    return off ^ ((off >> 3) & 0x70);
}
#define CP_ASYNC16(dst, src) \
    asm volatile("cp.async.cg.shared.global [%0], [%1], 16;" :: "r"(dst), "l"(src) : "memory")
#define CP_COMMIT() asm volatile("cp.async.commit_group;" ::: "memory")
#define CP_WAIT1()  asm volatile("cp.async.wait_group 1;" ::: "memory")

__device__ __forceinline__ void ldsm_x4(uint32_t& r0, uint32_t& r1, uint32_t& r2, uint32_t& r3,
                                        uint32_t addr) {
    asm volatile("ldmatrix.sync.aligned.m8n8.x4.shared.b16 {%0,%1,%2,%3}, [%4];"
                 : "=r"(r0), "=r"(r1), "=r"(r2), "=r"(r3) : "r"(addr));
}
__device__ __forceinline__ void imma16832(int32_t* c, const uint32_t* a, uint32_t b0, uint32_t b1) {
    asm volatile(
        "mma.sync.aligned.m16n8k32.row.col.s32.s8.s8.s32 "
        "{%0,%1,%2,%3}, {%4,%5,%6,%7}, {%8,%9}, {%0,%1,%2,%3};"
        : "+r"(c[0]), "+r"(c[1]), "+r"(c[2]), "+r"(c[3])
        : "r"(a[0]), "r"(a[1]), "r"(a[2]), "r"(a[3]), "r"(b0), "r"(b1));
}

// Supertiled mapping: groups of 8 N-tiles across all M-tiles (L2 reuse)
__device__ __forceinline__ void tile_mn(int t, int& m0, int& n0) {
    const int grp = t >> 10;       // / (128 m-tiles * 8)
    const int rem = t & 1023;
    m0 = (rem >> 3) * TM;
    n0 = ((grp << 3) + (rem & 7)) * TN;
}

// ---------------- merged prep kernel ----------------
__global__ void __launch_bounds__(256)
prep_kernel(const float* __restrict__ x, const int* __restrict__ wq,
            const float* __restrict__ zp_p) {
    const int b = blockIdx.x;
    const int tid = threadIdx.x;
    if (b < WBLOCKS) {
        const int zpr = lrintf(*zp_p);
        const size_t i = ((size_t)b * 256 + tid) * 4;
        int4 v = *reinterpret_cast<const int4*>(wq + i);
        char4 w;
        w.x = (char)(v.x - zpr);
        w.y = (char)(v.y - zpr);
        w.z = (char)(v.z - zpr);
        w.w = (char)(v.w - zpr);
        *reinterpret_cast<char4*>(&g_Bw[i]) = w;
    } else {
        __shared__ int red[8];
        const int xb = b - WBLOCKS;                    // quarter-row index
        const size_t i = ((size_t)xb * 256 + tid) * 4;
        float4 v = *reinterpret_cast<const float4*>(x + i);
        int q0 = min(max(__float2int_rn(v.x * QSCALE), -32640), 32639);
        int q1 = min(max(__float2int_rn(v.y * QSCALE), -32640), 32639);
        int q2 = min(max(__float2int_rn(v.z * QSCALE), -32640), 32639);
        int q3 = min(max(__float2int_rn(v.w * QSCALE), -32640), 32639);
        int h0 = (q0 + 128) >> 8, h1 = (q1 + 128) >> 8;
        int h2 = (q2 + 128) >> 8, h3 = (q3 + 128) >> 8;
        char4 hc, lc;
        hc.x = (char)h0; hc.y = (char)h1; hc.z = (char)h2; hc.w = (char)h3;
        lc.x = (char)(q0 - (h0 << 8)); lc.y = (char)(q1 - (h1 << 8));
        lc.z = (char)(q2 - (h2 << 8)); lc.w = (char)(q3 - (h3 << 8));
        *reinterpret_cast<char4*>(&g_Ah[i]) = hc;
        *reinterpret_cast<char4*>(&g_Al[i]) = lc;
        int s = q0 + q1 + q2 + q3;
#pragma unroll
        for (int o = 16; o; o >>= 1) s += __shfl_down_sync(0xFFFFFFFFu, s, o);
        if ((tid & 31) == 0) red[tid >> 5] = s;
        __syncthreads();
        if (tid == 0) {
            int t = red[0] + red[1] + red[2] + red[3] + red[4] + red[5] + red[6] + red[7];
            g_part[xb] = t;
        }
    }
}

// ---------------- persistent GEMM: 64x128 tiles, 8 warps (2m x 4n), s8 IMMA, 2 CTA/SM ----------------
__global__ void __launch_bounds__(THREADS, 2)
gemm_kernel(const float* __restrict__ bias, const float* __restrict__ scale_p,
            const float* __restrict__ zp_p, float* __restrict__ out) {
    extern __shared__ char smem[];
    const uint32_t sb = smem_u32(smem);
    const int tid = threadIdx.x;
    const int wid = tid >> 5;
    const int lane = tid & 31;
    const int bid = blockIdx.x;

    const int wm = wid >> 2;   // 0..1 -> 32 rows
    const int wn = wid & 3;    // 0..3 -> 32 cols

    // ---- cp.async mapping: 8x16B chunks per 128B row, 32 rows/pass ----
    const int chunk = tid & 7;
    const int row0 = tid >> 3;  // 0..31
    uint32_t dstA[2], dstB[4];
#pragma unroll
    for (int j = 0; j < 2; j++)
        dstA[j] = sw128((uint32_t)(row0 + 32 * j) * 128u + (uint32_t)chunk * 16u);
#pragma unroll
    for (int j = 0; j < 4; j++)
        dstB[j] = sw128((uint32_t)(row0 + 32 * j) * 128u + (uint32_t)chunk * 16u) + B_OFF;

    // ---- load-side state (uniform across CTA) ----
    int lt = bid;   // tile being loaded
    int lkc = 0;    // next k-chunk to load within lt
    const char *pAh, *pAl, *pB;
    auto set_load_tile = [&](int t) {
        int m0_, n0_;
        tile_mn(t, m0_, n0_);
        pAh = g_Ah + (size_t)m0_ * K_TOTAL + chunk * 16;
        pAl = g_Al + (size_t)m0_ * K_TOTAL + chunk * 16;
        pB  = g_Bw + (size_t)n0_ * K_TOTAL + chunk * 16;
    };
    set_load_tile(lt);

    auto load_chunk = [&](int buf) {
        const uint32_t tb = sb + (uint32_t)buf * STAGE_BYTES;
        const size_t koff = (size_t)lkc * KC;
#pragma unroll
        for (int j = 0; j < 2; j++) {
            const size_t roff = (size_t)(row0 + 32 * j) * K_TOTAL + koff;
            CP_ASYNC16(tb + AH_OFF + dstA[j], pAh + roff);
            CP_ASYNC16(tb + AL_OFF + dstA[j], pAl + roff);
        }
#pragma unroll
        for (int j = 0; j < 4; j++) {
            const size_t roff = (size_t)(row0 + 32 * j) * K_TOTAL + koff;
            CP_ASYNC16(tb + dstB[j], pB + roff);
        }
        CP_COMMIT();
        if (++lkc == NK) {
            lkc = 0;
            lt += GRID;
            if (lt < NT) set_load_tile(lt);
        }
    };

    // ---- ldmatrix lane addressing (int8: 16B column units) ----
    const int lmat = lane >> 3;
    const int lrow = lane & 7;
    uint32_t a_off[2];
#pragma unroll
    for (int tm = 0; tm < 2; tm++) {
        uint32_t r = (uint32_t)(wm * 32 + tm * 16 + lrow + ((lmat & 1) << 3));
        uint32_t c = (uint32_t)((lmat >> 1) << 4);
        a_off[tm] = sw128(r * 128u + c);
    }
    uint32_t b_off[2];
#pragma unroll
    for (int p = 0; p < 2; p++) {
        uint32_t r = (uint32_t)(wn * 32 + p * 16 + lrow + ((lmat >> 1) << 3));
        uint32_t c = (uint32_t)((lmat & 1) << 4);
        b_off[p] = sw128(r * 128u + c) + B_OFF;
    }

    int32_t acch[2][4][4], accl[2][4][4];
#pragma unroll
    for (int i = 0; i < 2; i++)
#pragma unroll
        for (int j = 0; j < 4; j++)
#pragma unroll
            for (int k = 0; k < 4; k++) { acch[i][j][k] = 0; accl[i][j][k] = 0; }

    uint32_t ah[2][4], al[2][4], rb0[4], rb1[4];

    // ---- prologue: 2 chunks in flight (3-stage, wait_group 1) ----
    load_chunk(0);
    load_chunk(1);

    const float sd = (*scale_p) * (1.0f / QSCALE);
    const float czp = (float)lrintf(*zp_p) - (*zp_p);

    int buf = 0;       // buffer holding chunk kc; cycles 0,1,2
    for (int ct = bid; ct < NT; ct += GRID) {
        int m0, n0;
        tile_mn(ct, m0, n0);

        for (int kc = 0; kc < NK; ++kc) {
            CP_WAIT1();            // chunk in `buf` resident (kc+1 may be pending)
            __syncthreads();       // all warps done reading buffer (buf+2)%3 (iter kc-1)
            if (lt < NT) {
                int nb = buf + 2; if (nb >= 3) nb -= 3;
                load_chunk(nb);    // load kc+2 into its buffer
            } else CP_COMMIT();    // keep wait_group accounting

            const uint32_t tb = sb + (uint32_t)buf * STAGE_BYTES;
#pragma unroll
            for (int ks = 0; ks < 4; ++ks) {
                const uint32_t kbyte = (uint32_t)ks * 32u;  // bits 5..6; XOR == add under sw128
#pragma unroll
                for (int p = 0; p < 2; p++) {
                    uint32_t r0, r1, r2, r3;
                    ldsm_x4(r0, r1, r2, r3, tb + (b_off[p] ^ kbyte));
                    rb0[2 * p] = r0;     rb1[2 * p] = r1;
                    rb0[2 * p + 1] = r2; rb1[2 * p + 1] = r3;
                }
#pragma unroll
                for (int tm = 0; tm < 2; tm++)
                    ldsm_x4(ah[tm][0], ah[tm][1], ah[tm][2], ah[tm][3],
                            tb + AH_OFF + (a_off[tm] ^ kbyte));
#pragma unroll
                for (int tm = 0; tm < 2; tm++)
                    ldsm_x4(al[tm][0], al[tm][1], al[tm][2], al[tm][3],
                            tb + AL_OFF + (a_off[tm] ^ kbyte));
#pragma unroll
                for (int tm = 0; tm < 2; tm++)
#pragma unroll
                    for (int tn = 0; tn < 4; tn++) {
                        imma16832(acch[tm][tn], ah[tm], rb0[tn], rb1[tn]);
                        imma16832(accl[tm][tn], al[tm], rb0[tn], rb1[tn]);
                    }
            }
            if (++buf == 3) buf = 0;
        }

        // ---- epilogue: y = (256*Sh + Sl + c*rowsum_q)*(scale/2048) + bias ----
        const int r_base = m0 + wm * 32 + (lane >> 2);
        const int c_base = n0 + wn * 32 + (lane & 3) * 2;
#pragma unroll
        for (int tm = 0; tm < 2; tm++) {
            const int row = r_base + tm * 16;
            const int rs0 = g_part[row * 4] + g_part[row * 4 + 1]
                          + g_part[row * 4 + 2] + g_part[row * 4 + 3];
            const int rs1 = g_part[(row + 8) * 4] + g_part[(row + 8) * 4 + 1]
                          + g_part[(row + 8) * 4 + 2] + g_part[(row + 8) * 4 + 3];
            const float radd0 = czp * (float)rs0 * sd;
            const float radd1 = czp * (float)rs1 * sd;
#pragma unroll
            for (int tn = 0; tn < 4; tn++) {
                const int col = c_base + tn * 8;
                const float2 bv = *reinterpret_cast<const float2*>(bias + col);
                float t0 = fmaf(256.0f, (float)acch[tm][tn][0], (float)accl[tm][tn][0]);
                float t1 = fmaf(256.0f, (float)acch[tm][tn][1], (float)accl[tm][tn][1]);
                float t2 = fmaf(256.0f, (float)acch[tm][tn][2], (float)accl[tm][tn][2]);
                float t3 = fmaf(256.0f, (float)acch[tm][tn][3], (float)accl[tm][tn][3]);
                float2 o0, o1;
                o0.x = fmaf(t0, sd, bv.x + radd0);
                o0.y = fmaf(t1, sd, bv.y + radd0);
                o1.x = fmaf(t2, sd, bv.x + radd1);
                o1.y = fmaf(t3, sd, bv.y + radd1);
                *reinterpret_cast<float2*>(out + (size_t)row * N_TOTAL + col) = o0;
                *reinterpret_cast<float2*>(out + (size_t)(row + 8) * N_TOTAL + col) = o1;
                acch[tm][tn][0] = 0; acch[tm][tn][1] = 0; acch[tm][tn][2] = 0; acch[tm][tn][3] = 0;
                accl[tm][tn][0] = 0; accl[tm][tn][1] = 0; accl[tm][tn][2] = 0; accl[tm][tn][3] = 0;
            }
        }
    }
}

// ---------------- launch ----------------
extern "C" void kernel_launch(void* const* d_in, const int* in_sizes, int n_in,
                              void* d_out, int out_size) {
    const float* x     = (const float*)d_in[0];
    const int*   wq    = (const int*)  d_in[1];
    const float* bias  = (const float*)d_in[2];
    const float* scale = (const float*)d_in[3];
    const float* zp    = (const float*)d_in[4];
    float* out = (float*)d_out;

    cudaFuncSetAttribute(gemm_kernel, cudaFuncAttributeMaxDynamicSharedMemorySize, SMEM_BYTES);

    prep_kernel<<<WBLOCKS + XBLOCKS, 256>>>(x, wq, zp);
    gemm_kernel<<<GRID, THREADS, SMEM_BYTES>>>(bias, scale, zp, out);
}

// round 13
// speedup vs baseline: 1.0731x; 1.0083x over previous
#include <cuda_runtime.h>
#include <cstdint>

// y = x @ (scale*(Wq - zp))^T + bias
// x [8192,4096] fp32, Wq [4096,4096] i32, out [8192,4096] fp32.
#define M_TOTAL 8192
#define K_TOTAL 4096
#define N_TOTAL 4096

static constexpr int TM = 64;
static constexpr int TN = 128;
static constexpr int KC = 128;           // 128 int8 = 128B rows (one SW128 block)
static constexpr int NK = K_TOTAL / KC;  // 32
static constexpr int NT = (M_TOTAL / TM) * (N_TOTAL / TN);  // 4096 tiles
static constexpr int GRID = 296;         // persistent: two CTAs per SM
static constexpr int THREADS = 256;      // 8 warps: 2m x 4n, 32x32 warp tiles
static constexpr int AH_OFF = 0;
static constexpr int AL_OFF = 8192;
static constexpr int B_OFF  = 16384;
static constexpr int STAGE_BYTES = 32768;               // Ah 8K + Al 8K + B 16K
static constexpr int SMEM_BYTES = 3 * STAGE_BYTES;      // 98304 (x2 CTAs = 192KB/SM)

// x quantization: q = round(x*2048), q = 256*h + l (h,l int8)
static constexpr float QSCALE = 2048.0f;

// prep grid split: W blocks then X blocks (1024 elems per block each)
static constexpr int WBLOCKS = (N_TOTAL * K_TOTAL) / 1024;          // 16384
static constexpr int XBLOCKS = (M_TOTAL * K_TOTAL) / 1024;          // 32768
static constexpr int QROWS   = M_TOTAL * 4;                         // quarter-rows

// ---------------- scratch (device globals: allocation-free) ----------------
__device__ __align__(1024) char g_Ah[(size_t)M_TOTAL * K_TOTAL];  // 32 MB
__device__ __align__(1024) char g_Al[(size_t)M_TOTAL * K_TOTAL];  // 32 MB
__device__ __align__(1024) char g_Bw[(size_t)N_TOTAL * K_TOTAL];  // 16 MB
__device__ int g_part[QROWS];   // per-quarter-row q sums (plain stores, no init needed)

// ---------------- helpers ----------------
__device__ __forceinline__ uint32_t smem_u32(const void* p) {
    uint32_t a;
    asm("{ .reg .u64 t; cvta.to.shared.u64 t, %1; cvt.u32.u64 %0, t; }" : "=r"(a) : "l"(p));
    return a;
}
__device__ __forceinline__ uint32_t sw128(uint32_t off) {
    return off ^ ((off >> 3) & 0x70);
}
#define CP_ASYNC16(dst, src) \
    asm volatile("cp.async.cg.shared.global [%0], [%1], 16;" :: "r"(dst), "l"(src) : "memory")
#define CP_COMMIT() asm volatile("cp.async.commit_group;" ::: "memory")
#define CP_WAIT1()  asm volatile("cp.async.wait_group 1;" ::: "memory")

__device__ __forceinline__ void ldsm_x4(uint32_t& r0, uint32_t& r1, uint32_t& r2, uint32_t& r3,
                                        uint32_t addr) {
    asm volatile("ldmatrix.sync.aligned.m8n8.x4.shared.b16 {%0,%1,%2,%3}, [%4];"
                 : "=r"(r0), "=r"(r1), "=r"(r2), "=r"(r3) : "r"(addr));
}
__device__ __forceinline__ void imma16832(int32_t* c, const uint32_t* a, uint32_t b0, uint32_t b1) {
    asm volatile(
        "mma.sync.aligned.m16n8k32.row.col.s32.s8.s8.s32 "
        "{%0,%1,%2,%3}, {%4,%5,%6,%7}, {%8,%9}, {%0,%1,%2,%3};"
        : "+r"(c[0]), "+r"(c[1]), "+r"(c[2]), "+r"(c[3])
        : "r"(a[0]), "r"(a[1]), "r"(a[2]), "r"(a[3]), "r"(b0), "r"(b1));
}

// Supertiled mapping: groups of 8 N-tiles across all M-tiles (L2 reuse)
__device__ __forceinline__ void tile_mn(int t, int& m0, int& n0) {
    const int grp = t >> 10;       // / (128 m-tiles * 8)
    const int rem = t & 1023;
    m0 = (rem >> 3) * TM;
    n0 = ((grp << 3) + (rem & 7)) * TN;
}

// ---------------- merged prep kernel ----------------
__global__ void __launch_bounds__(256)
prep_kernel(const float* __restrict__ x, const int* __restrict__ wq,
            const float* __restrict__ zp_p) {
    const int b = blockIdx.x;
    const int tid = threadIdx.x;
    if (b < WBLOCKS) {
        const int zpr = lrintf(*zp_p);
        const size_t i = ((size_t)b * 256 + tid) * 4;
        int4 v = *reinterpret_cast<const int4*>(wq + i);
        char4 w;
        w.x = (char)(v.x - zpr);
        w.y = (char)(v.y - zpr);
        w.z = (char)(v.z - zpr);
        w.w = (char)(v.w - zpr);
        *reinterpret_cast<char4*>(&g_Bw[i]) = w;
    } else {
        __shared__ int red[8];
        const int xb = b - WBLOCKS;                    // quarter-row index
        const size_t i = ((size_t)xb * 256 + tid) * 4;
        float4 v = *reinterpret_cast<const float4*>(x + i);
        int q0 = min(max(__float2int_rn(v.x * QSCALE), -32640), 32639);
        int q1 = min(max(__float2int_rn(v.y * QSCALE), -32640), 32639);
        int q2 = min(max(__float2int_rn(v.z * QSCALE), -32640), 32639);
        int q3 = min(max(__float2int_rn(v.w * QSCALE), -32640), 32639);
        int h0 = (q0 + 128) >> 8, h1 = (q1 + 128) >> 8;
        int h2 = (q2 + 128) >> 8, h3 = (q3 + 128) >> 8;
        char4 hc, lc;
        hc.x = (char)h0; hc.y = (char)h1; hc.z = (char)h2; hc.w = (char)h3;
        lc.x = (char)(q0 - (h0 << 8)); lc.y = (char)(q1 - (h1 << 8));
        lc.z = (char)(q2 - (h2 << 8)); lc.w = (char)(q3 - (h3 << 8));
        *reinterpret_cast<char4*>(&g_Ah[i]) = hc;
        *reinterpret_cast<char4*>(&g_Al[i]) = lc;
        int s = q0 + q1 + q2 + q3;
#pragma unroll
        for (int o = 16; o; o >>= 1) s += __shfl_down_sync(0xFFFFFFFFu, s, o);
        if ((tid & 31) == 0) red[tid >> 5] = s;
        __syncthreads();
        if (tid == 0) {
            int t = red[0] + red[1] + red[2] + red[3] + red[4] + red[5] + red[6] + red[7];
            g_part[xb] = t;
        }
    }
}

// ---------------- persistent GEMM: 64x128 tiles, 8 warps (2m x 4n), s8 IMMA, 2 CTA/SM ----------------
__global__ void __launch_bounds__(THREADS, 2)
gemm_kernel(const float* __restrict__ bias, const float* __restrict__ scale_p,
            const float* __restrict__ zp_p, float* __restrict__ out) {
    extern __shared__ char smem[];
    const uint32_t sb = smem_u32(smem);
    const int tid = threadIdx.x;
    const int wid = tid >> 5;
    const int lane = tid & 31;
    const int bid = blockIdx.x;

    const int wm = wid >> 2;   // 0..1 -> 32 rows
    const int wn = wid & 3;    // 0..3 -> 32 cols
    // ks phase rotation: the two warps sharing one SMSP (wid, wid+4) start
    // their k-step loop 2 steps apart so their LDSM bursts interleave with
    // the other's MMA drain. All 4 ks of a chunk are resident, any order OK.
    const int ks0 = (wid >> 2) * 2;

    // ---- cp.async mapping: 8x16B chunks per 128B row, 32 rows/pass ----
    const int chunk = tid & 7;
    const int row0 = tid >> 3;  // 0..31
    uint32_t dstA[2], dstB[4];
#pragma unroll
    for (int j = 0; j < 2; j++)
        dstA[j] = sw128((uint32_t)(row0 + 32 * j) * 128u + (uint32_t)chunk * 16u);
#pragma unroll
    for (int j = 0; j < 4; j++)
        dstB[j] = sw128((uint32_t)(row0 + 32 * j) * 128u + (uint32_t)chunk * 16u) + B_OFF;

    // ---- load-side state (uniform across CTA) ----
    int lt = bid;   // tile being loaded
    int lkc = 0;    // next k-chunk to load within lt
    const char *pAh, *pAl, *pB;
    auto set_load_tile = [&](int t) {
        int m0_, n0_;
        tile_mn(t, m0_, n0_);
        pAh = g_Ah + (size_t)m0_ * K_TOTAL + chunk * 16;
        pAl = g_Al + (size_t)m0_ * K_TOTAL + chunk * 16;
        pB  = g_Bw + (size_t)n0_ * K_TOTAL + chunk * 16;
    };
    set_load_tile(lt);

    auto load_chunk = [&](int buf) {
        const uint32_t tb = sb + (uint32_t)buf * STAGE_BYTES;
        const size_t koff = (size_t)lkc * KC;
#pragma unroll
        for (int j = 0; j < 2; j++) {
            const size_t roff = (size_t)(row0 + 32 * j) * K_TOTAL + koff;
            CP_ASYNC16(tb + AH_OFF + dstA[j], pAh + roff);
            CP_ASYNC16(tb + AL_OFF + dstA[j], pAl + roff);
        }
#pragma unroll
        for (int j = 0; j < 4; j++) {
            const size_t roff = (size_t)(row0 + 32 * j) * K_TOTAL + koff;
            CP_ASYNC16(tb + dstB[j], pB + roff);
        }
        CP_COMMIT();
        if (++lkc == NK) {
            lkc = 0;
            lt += GRID;
            if (lt < NT) set_load_tile(lt);
        }
    };

    // ---- ldmatrix lane addressing (int8: 16B column units) ----
    const int lmat = lane >> 3;
    const int lrow = lane & 7;
    uint32_t a_off[2];
#pragma unroll
    for (int tm = 0; tm < 2; tm++) {
        uint32_t r = (uint32_t)(wm * 32 + tm * 16 + lrow + ((lmat & 1) << 3));
        uint32_t c = (uint32_t)((lmat >> 1) << 4);
        a_off[tm] = sw128(r * 128u + c);
    }
    uint32_t b_off[2];
#pragma unroll
    for (int p = 0; p < 2; p++) {
        uint32_t r = (uint32_t)(wn * 32 + p * 16 + lrow + ((lmat >> 1) << 3));
        uint32_t c = (uint32_t)((lmat & 1) << 4);
        b_off[p] = sw128(r * 128u + c) + B_OFF;
    }

    int32_t acch[2][4][4], accl[2][4][4];
#pragma unroll
    for (int i = 0; i < 2; i++)
#pragma unroll
        for (int j = 0; j < 4; j++)
#pragma unroll
            for (int k = 0; k < 4; k++) { acch[i][j][k] = 0; accl[i][j][k] = 0; }

    uint32_t ah[2][4], al[2][4], rb0[4], rb1[4];

    // ---- prologue: 2 chunks in flight (3-stage, wait_group 1) ----
    load_chunk(0);
    load_chunk(1);

    const float sd = (*scale_p) * (1.0f / QSCALE);
    const float czp = (float)lrintf(*zp_p) - (*zp_p);

    int buf = 0;       // buffer holding chunk kc; cycles 0,1,2
    for (int ct = bid; ct < NT; ct += GRID) {
        int m0, n0;
        tile_mn(ct, m0, n0);

        for (int kc = 0; kc < NK; ++kc) {
            CP_WAIT1();            // chunk in `buf` resident (kc+1 may be pending)
            __syncthreads();       // all warps done reading buffer (buf+2)%3 (iter kc-1)
            if (lt < NT) {
                int nb = buf + 2; if (nb >= 3) nb -= 3;
                load_chunk(nb);    // load kc+2 into its buffer
            } else CP_COMMIT();    // keep wait_group accounting

            const uint32_t tb = sb + (uint32_t)buf * STAGE_BYTES;
#pragma unroll
            for (int kk = 0; kk < 4; ++kk) {
                const int ks = (kk + ks0) & 3;
                const uint32_t kbyte = (uint32_t)ks * 32u;  // bits 5..6; XOR == add under sw128
#pragma unroll
                for (int p = 0; p < 2; p++) {
                    uint32_t r0, r1, r2, r3;
                    ldsm_x4(r0, r1, r2, r3, tb + (b_off[p] ^ kbyte));
                    rb0[2 * p] = r0;     rb1[2 * p] = r1;
                    rb0[2 * p + 1] = r2; rb1[2 * p + 1] = r3;
                }
#pragma unroll
                for (int tm = 0; tm < 2; tm++)
                    ldsm_x4(ah[tm][0], ah[tm][1], ah[tm][2], ah[tm][3],
                            tb + AH_OFF + (a_off[tm] ^ kbyte));
#pragma unroll
                for (int tm = 0; tm < 2; tm++)
                    ldsm_x4(al[tm][0], al[tm][1], al[tm][2], al[tm][3],
                            tb + AL_OFF + (a_off[tm] ^ kbyte));
                // all h-MMAs first (deps ready earliest), then l-MMAs:
                // gives the al LDSMs ~8 MMA issue slots of extra latency cover.
#pragma unroll
                for (int tm = 0; tm < 2; tm++)
#pragma unroll
                    for (int tn = 0; tn < 4; tn++)
                        imma16832(acch[tm][tn], ah[tm], rb0[tn], rb1[tn]);
#pragma unroll
                for (int tm = 0; tm < 2; tm++)
#pragma unroll
                    for (int tn = 0; tn < 4; tn++)
                        imma16832(accl[tm][tn], al[tm], rb0[tn], rb1[tn]);
            }
            if (++buf == 3) buf = 0;
        }

        // ---- epilogue: y = (256*Sh + Sl + c*rowsum_q)*(scale/2048) + bias ----
        const int r_base = m0 + wm * 32 + (lane >> 2);
        const int c_base = n0 + wn * 32 + (lane & 3) * 2;
#pragma unroll
        for (int tm = 0; tm < 2; tm++) {
            const int row = r_base + tm * 16;
            const int rs0 = g_part[row * 4] + g_part[row * 4 + 1]
                          + g_part[row * 4 + 2] + g_part[row * 4 + 3];
            const int rs1 = g_part[(row + 8) * 4] + g_part[(row + 8) * 4 + 1]
                          + g_part[(row + 8) * 4 + 2] + g_part[(row + 8) * 4 + 3];
            const float radd0 = czp * (float)rs0 * sd;
            const float radd1 = czp * (float)rs1 * sd;
#pragma unroll
            for (int tn = 0; tn < 4; tn++) {
                const int col = c_base + tn * 8;
                const float2 bv = *reinterpret_cast<const float2*>(bias + col);
                float t0 = fmaf(256.0f, (float)acch[tm][tn][0], (float)accl[tm][tn][0]);
                float t1 = fmaf(256.0f, (float)acch[tm][tn][1], (float)accl[tm][tn][1]);
                float t2 = fmaf(256.0f, (float)acch[tm][tn][2], (float)accl[tm][tn][2]);
                float t3 = fmaf(256.0f, (float)acch[tm][tn][3], (float)accl[tm][tn][3]);
                float2 o0, o1;
                o0.x = fmaf(t0, sd, bv.x + radd0);
                o0.y = fmaf(t1, sd, bv.y + radd0);
                o1.x = fmaf(t2, sd, bv.x + radd1);
                o1.y = fmaf(t3, sd, bv.y + radd1);
                *reinterpret_cast<float2*>(out + (size_t)row * N_TOTAL + col) = o0;
                *reinterpret_cast<float2*>(out + (size_t)(row + 8) * N_TOTAL + col) = o1;
                acch[tm][tn][0] = 0; acch[tm][tn][1] = 0; acch[tm][tn][2] = 0; acch[tm][tn][3] = 0;
                accl[tm][tn][0] = 0; accl[tm][tn][1] = 0; accl[tm][tn][2] = 0; accl[tm][tn][3] = 0;
            }
        }
    }
}

// ---------------- launch ----------------
extern "C" void kernel_launch(void* const* d_in, const int* in_sizes, int n_in,
                              void* d_out, int out_size) {
    const float* x     = (const float*)d_in[0];
    const int*   wq    = (const int*)  d_in[1];
    const float* bias  = (const float*)d_in[2];
    const float* scale = (const float*)d_in[3];
    const float* zp    = (const float*)d_in[4];
    float* out = (float*)d_out;

    cudaFuncSetAttribute(gemm_kernel, cudaFuncAttributeMaxDynamicSharedMemorySize, SMEM_BYTES);

    prep_kernel<<<WBLOCKS + XBLOCKS, 256>>>(x, wq, zp);
    gemm_kernel<<<GRID, THREADS, SMEM_BYTES>>>(bias, scale, zp, out);
}